// round 7
// baseline (speedup 1.0000x reference)
#include <cuda_runtime.h>
#include <cstdint>

#define E_    12
#define D_    768
#define KDIM  1536
#define NE    24
#define ROWS  40            // batch rows per CTA tile (K1): 410 tiles -> single wave
#define KC    128           // K chunk
#define NCH   12            // KDIM / KC
#define GSTR  132           // G row stride (floats): 528B == 16 mod 128 -> conflict-free
#define WSTR  132           // W chunk row stride
#define GBUF  (ROWS * GSTR) // 5280 floats
#define WBUF  (NE * WSTR)   // 3168 floats
#define BMAX  16384

// Cross-kernel handoff (static device arrays — allocation-free)
__device__ float g_scl[2 * BMAX];
__device__ int   g_idx[2 * BMAX];

__device__ __forceinline__ void ffma2(unsigned long long &d,
                                      unsigned long long a,
                                      unsigned long long b) {
    asm("fma.rn.f32x2 %0, %1, %2, %0;" : "+l"(d) : "l"(a), "l"(b));
}
__device__ __forceinline__ float2 unpack2(unsigned long long v) {
    float2 r;
    asm("mov.b64 {%0, %1}, %2;" : "=f"(r.x), "=f"(r.y) : "l"(v));
    return r;
}
__device__ __forceinline__ void cp16(uint32_t dst, const float* src) {
    asm volatile("cp.async.cg.shared.global [%0], [%1], 16;" :: "r"(dst), "l"(src));
}

// ── Kernel 1: cp.async-pipelined logits GEMM (5x6 reg tile) + gumbel-softmax-ST ──
__global__ void __launch_bounds__(256, 3) gate_logits(
    const float* __restrict__ audio, const float* __restrict__ image,
    const float* __restrict__ Wa,    const float* __restrict__ ba,
    const float* __restrict__ Wi,    const float* __restrict__ bi,
    const float* __restrict__ ga,    const float* __restrict__ gi,
    float* __restrict__ out, int B)
{
    extern __shared__ float sm[];
    float* Gm = sm;                    // 2 x GBUF (double buffer)
    float* Wm = sm + 2 * GBUF;         // 2 x WBUF (double buffer)
    float* Ls = Wm + 2 * WBUF;         // ROWS x NE reduced logits
    float* Lp = Gm;                    // alias: 8 x ROWS x NE partials (7680 <= 2*GBUF)

    const int tid  = threadIdx.x;
    const int lane = tid & 31;
    const int ksl  = tid >> 5;         // warp = K-slice: floats ksl*16 .. +15 per chunk
    const int eg   = lane >> 3;        // expert group: experts eg*6 .. eg*6+5
    const int rp   = lane & 7;         // rows rp, rp+8, rp+16, rp+24, rp+32
    const int row0 = blockIdx.x * ROWS;

    const uint32_t gsm = (uint32_t)__cvta_generic_to_shared(Gm);
    const uint32_t wsm = (uint32_t)__cvta_generic_to_shared(Wm);
    const size_t rowstride = (size_t)E_ * D_;   // 9216

    unsigned long long acc[5][6];
    #pragma unroll
    for (int j = 0; j < 5; j++)
        #pragma unroll
        for (int m = 0; m < 6; m++) acc[j][m] = 0ULL;

    auto stage = [&](int c) {
        const int buf = c & 1;
        const float* src = (c < NCH / 2) ? audio : image;
        const int kb = (c < NCH / 2) ? c * KC : c * KC - D_;
        #pragma unroll
        for (int j = 0; j < 5; j++) {            // G: 1280 quads, 5/thread
            int i = tid + j * 256;
            int r = i >> 5, q = i & 31;
            int b = row0 + r; if (b >= B) b = B - 1;
            cp16(gsm + (uint32_t)((buf * GBUF + r * GSTR + q * 4) * 4),
                 src + (size_t)b * rowstride + kb + q * 4);
        }
        #pragma unroll
        for (int j = 0; j < 3; j++) {            // W: 768 quads, 3/thread
            int i = tid + j * 256;
            int e = i >> 5, q = i & 31;
            const float* ws = (e < E_) ? Wa + (size_t)e * KDIM
                                       : Wi + (size_t)(e - E_) * KDIM;
            cp16(wsm + (uint32_t)((buf * WBUF + e * WSTR + q * 4) * 4),
                 ws + c * KC + q * 4);
        }
        asm volatile("cp.async.commit_group;");
    };

    stage(0);

    for (int c = 0; c < NCH; c++) {
        if (c + 1 < NCH) {
            stage(c + 1);
            asm volatile("cp.async.wait_group 1;");
        } else {
            asm volatile("cp.async.wait_group 0;");
        }
        __syncthreads();

        const float* gb = Gm + (c & 1) * GBUF;
        const float* wb = Wm + (c & 1) * WBUF;
        const int cb = ksl * 16;
        #pragma unroll
        for (int kk = 0; kk < 4; kk++) {
            const int col = cb + kk * 4;
            ulonglong2 g[5];
            #pragma unroll
            for (int j = 0; j < 5; j++)
                g[j] = *(const ulonglong2*)(gb + (rp + 8 * j) * GSTR + col);
            #pragma unroll
            for (int m = 0; m < 6; m++) {
                ulonglong2 w = *(const ulonglong2*)(wb + (eg * 6 + m) * WSTR + col);
                #pragma unroll
                for (int j = 0; j < 5; j++) {
                    ffma2(acc[j][m], g[j].x, w.x);
                    ffma2(acc[j][m], g[j].y, w.y);
                }
            }
        }
        __syncthreads();   // all reads done before restage / Lp alias
    }

    // Deposit split-K partials (deterministic order)
    #pragma unroll
    for (int j = 0; j < 5; j++)
        #pragma unroll
        for (int m = 0; m < 6; m++) {
            float2 p = unpack2(acc[j][m]);
            Lp[(ksl * ROWS + rp + 8 * j) * NE + eg * 6 + m] = p.x + p.y;
        }
    __syncthreads();

    // Reduce 8 K-slices in fixed order: 960 sums
    #pragma unroll
    for (int t = 0; t < 4; t++) {
        int idx = tid + t * 256;
        if (idx < ROWS * NE) {
            int r = idx / NE;
            int e = idx - r * NE;
            float s = 0.f;
            #pragma unroll
            for (int k = 0; k < 8; k++) s += Lp[(k * ROWS + r) * NE + e];
            Ls[r * NE + e] = s;
        }
    }
    __syncthreads();

    // Gumbel-softmax straight-through (one thread per row)
    if (tid < ROWS) {
        int b = row0 + tid;
        if (b < B) {
            float* retA = out + (size_t)B * KDIM;
            float* retI = retA + (size_t)B * E_;
            #pragma unroll
            for (int gsel = 0; gsel < 2; gsel++) {
                const float* bias = gsel ? bi : ba;
                const float* gum  = gsel ? gi : ga;
                float* retp       = gsel ? retI : retA;
                float l[E_];
                float mx = -1e30f;
                #pragma unroll
                for (int e = 0; e < E_; e++) {
                    l[e] = Ls[tid * NE + gsel * E_ + e] + bias[e]
                         + gum[(size_t)b * E_ + e];
                    mx = fmaxf(mx, l[e]);
                }
                float s = 0.f;
                float y[E_];
                #pragma unroll
                for (int e = 0; e < E_; e++) { y[e] = expf(l[e] - mx); s += y[e]; }
                const float inv = 1.0f / s;
                float ys[E_];
                int   am = 0;
                float best = y[0] * inv;
                ys[0] = best;
                #pragma unroll
                for (int e = 1; e < E_; e++) {
                    ys[e] = y[e] * inv;
                    if (ys[e] > best) { best = ys[e]; am = e; }  // first-max (jnp.argmax)
                }
                #pragma unroll
                for (int e = 0; e < E_; e++) {
                    float h = (e == am) ? 1.0f : 0.0f;
                    retp[(size_t)b * E_ + e] = (h - ys[e]) + ys[e];  // exact ref arithmetic
                }
                g_scl[gsel * BMAX + b] = ((1.0f - ys[am]) + ys[am]) * (1.0f / 12.0f);
                g_idx[gsel * BMAX + b] = am;
            }
        }
    }
}

// ── Kernel 2: gather — warp per row, 12 independent LDG.128 per lane ──
__global__ void __launch_bounds__(256) gate_gather(
    const float* __restrict__ audio, const float* __restrict__ image,
    float* __restrict__ out, int B)
{
    const int wid  = threadIdx.x >> 5;
    const int lane = threadIdx.x & 31;
    const int b    = blockIdx.x * 8 + wid;
    if (b >= B) return;

    const float sa = g_scl[b];
    const float si = g_scl[BMAX + b];
    const int   ia = g_idx[b];
    const int   ii = g_idx[BMAX + b];

    const float* ap = audio + ((size_t)b * E_ + ia) * D_;
    const float* ip = image + ((size_t)b * E_ + ii) * D_;
    float*       op = out + (size_t)b * KDIM;

    float4 v[12];
    #pragma unroll
    for (int j = 0; j < 6; j++)
        v[j] = *(const float4*)(ap + (lane + 32 * j) * 4);
    #pragma unroll
    for (int j = 0; j < 6; j++)
        v[6 + j] = *(const float4*)(ip + (lane + 32 * j) * 4);

    #pragma unroll
    for (int j = 0; j < 6; j++) {
        float4 t = v[j];
        t.x *= sa; t.y *= sa; t.z *= sa; t.w *= sa;
        *(float4*)(op + (lane + 32 * j) * 4) = t;
    }
    #pragma unroll
    for (int j = 0; j < 6; j++) {
        float4 t = v[6 + j];
        t.x *= si; t.y *= si; t.z *= si; t.w *= si;
        *(float4*)(op + D_ + (lane + 32 * j) * 4) = t;
    }
}

#define SMEM_BYTES ((2 * GBUF + 2 * WBUF + ROWS * NE) * 4)   // 71,424 B

extern "C" void kernel_launch(void* const* d_in, const int* in_sizes, int n_in,
                              void* d_out, int out_size) {
    const float* audio = (const float*)d_in[0];
    const float* image = (const float*)d_in[1];
    const float* Wa    = (const float*)d_in[2];
    const float* ba    = (const float*)d_in[3];
    const float* Wi    = (const float*)d_in[4];
    const float* bi    = (const float*)d_in[5];
    const float* ga    = (const float*)d_in[6];
    const float* gi    = (const float*)d_in[7];
    float* out = (float*)d_out;

    const int B = in_sizes[0] / (E_ * D_);     // 16384

    static bool attr_set = false;
    if (!attr_set) {
        cudaFuncSetAttribute(gate_logits,
                             cudaFuncAttributeMaxDynamicSharedMemorySize, SMEM_BYTES);
        attr_set = true;
    }

    const int grid1 = (B + ROWS - 1) / ROWS;   // 410 -> single wave at 3 CTAs/SM
    gate_logits<<<grid1, 256, SMEM_BYTES>>>(audio, image, Wa, ba, Wi, bi,
                                            ga, gi, out, B);

    const int grid2 = (B + 7) / 8;             // 2048
    gate_gather<<<grid2, 256>>>(audio, image, out, B);
}

// round 8
// speedup vs baseline: 1.3947x; 1.3947x over previous
#include <cuda_runtime.h>
#include <cstdint>

#define E_    12
#define D_    768
#define KDIM  1536
#define NE    24
#define ROWS  32            // batch rows per CTA tile (K1)
#define KC    128           // K chunk
#define NCH   12            // KDIM / KC
#define GSTR  132           // G row stride (floats): 528B == 16 mod 128 -> conflict-free
#define WSTR  132           // W chunk row stride
#define GBUF  (ROWS * GSTR) // 4224 floats
#define WBUF  (NE * WSTR)   // 3168 floats
#define BMAX  16384

// Cross-kernel handoff (static device arrays — allocation-free)
__device__ float g_scl[2 * BMAX];
__device__ int   g_idx[2 * BMAX];

__device__ __forceinline__ void ffma2(unsigned long long &d,
                                      unsigned long long a,
                                      unsigned long long b) {
    asm("fma.rn.f32x2 %0, %1, %2, %0;" : "+l"(d) : "l"(a), "l"(b));
}
__device__ __forceinline__ float2 unpack2(unsigned long long v) {
    float2 r;
    asm("mov.b64 {%0, %1}, %2;" : "=f"(r.x), "=f"(r.y) : "l"(v));
    return r;
}
__device__ __forceinline__ void bulk512(uint32_t dst, const float* src, uint32_t mbar) {
    asm volatile(
        "cp.async.bulk.shared::cluster.global.mbarrier::complete_tx::bytes "
        "[%0], [%1], 512, [%2];"
        :: "r"(dst), "l"(src), "r"(mbar) : "memory");
}
__device__ __forceinline__ void expect_tx(uint32_t mbar, uint32_t bytes) {
    asm volatile("mbarrier.arrive.expect_tx.shared.b64 _, [%0], %1;"
                 :: "r"(mbar), "r"(bytes) : "memory");
}
__device__ __forceinline__ void wait_parity(uint32_t mbar, uint32_t parity) {
    uint32_t done;
    asm volatile(
        "{\n\t.reg .pred p;\n\t"
        "mbarrier.try_wait.parity.acquire.cta.shared::cta.b64 p, [%1], %2;\n\t"
        "selp.b32 %0, 1, 0, p;\n\t}"
        : "=r"(done) : "r"(mbar), "r"(parity) : "memory");
    if (!done) {
        asm volatile(
            "{\n\t.reg .pred P1;\n\t"
            "WL_%=:\n\t"
            "mbarrier.try_wait.parity.acquire.cta.shared::cta.b64 P1, [%0], %1, 0x989680;\n\t"
            "@P1 bra.uni WD_%=;\n\t"
            "bra.uni WL_%=;\n\t"
            "WD_%=:\n\t}"
            :: "r"(mbar), "r"(parity) : "memory");
    }
}

// ── Kernel 1: bulk-async double-buffered logits GEMM + gumbel-softmax-ST ──
__global__ void __launch_bounds__(256, 3) gate_logits(
    const float* __restrict__ audio, const float* __restrict__ image,
    const float* __restrict__ Wa,    const float* __restrict__ ba,
    const float* __restrict__ Wi,    const float* __restrict__ bi,
    const float* __restrict__ ga,    const float* __restrict__ gi,
    float* __restrict__ out, int B)
{
    extern __shared__ float sm[];
    float* Gm = sm;                    // 2 x GBUF (double buffer)
    float* Wm = sm + 2 * GBUF;         // 2 x WBUF (double buffer)
    float* Ls = Wm + 2 * WBUF;         // ROWS x NE reduced logits
    float* Lp = Gm;                    // alias: 4 x ROWS x NE split-K partials
    uint32_t mb0;                      // smem addr of mbar[0]; mbar[1] at +8
    {
        uint64_t* mb = (uint64_t*)(Ls + ROWS * NE);
        mb0 = (uint32_t)__cvta_generic_to_shared(mb);
    }

    const int tid  = threadIdx.x;
    const int lane = tid & 31;
    const int wid  = tid >> 5;
    const int ksl  = wid & 3;          // K-slice: floats ksl*32 .. +31 of each chunk
    const int rh   = wid >> 2;         // row half (0..1)
    const int rp   = lane >> 2;        // row pair base (0..7)
    const int eg   = lane & 3;         // expert group: experts eg*6 .. eg*6+5
    const int r0   = rh * 16 + rp;     // rows r0, r0+8
    const int row0 = blockIdx.x * ROWS;

    const uint32_t gsm = (uint32_t)__cvta_generic_to_shared(Gm);
    const uint32_t wsm = (uint32_t)__cvta_generic_to_shared(Wm);
    const size_t rowstride = (size_t)E_ * D_;   // 9216

    // Init mbarriers: 56 arrivals per phase (one per issuing thread)
    if (tid == 0) {
        asm volatile("mbarrier.init.shared.b64 [%0], 56;" :: "r"(mb0) : "memory");
        asm volatile("mbarrier.init.shared.b64 [%0], 56;" :: "r"(mb0 + 8) : "memory");
        asm volatile("fence.proxy.async.shared::cta;" ::: "memory");
    }
    __syncthreads();

    // Per-thread staging source (fixed role): tid<32 -> G row, 32<=tid<56 -> W row
    const float* gsrc_a = nullptr;  // audio row for this thread's G role
    const float* gsrc_i = nullptr;
    const float* wsrc   = nullptr;
    uint32_t     dG = 0, dW = 0;
    if (tid < 32) {
        int b = row0 + tid; if (b >= B) b = B - 1;
        gsrc_a = audio + (size_t)b * rowstride;
        gsrc_i = image + (size_t)b * rowstride;
        dG = gsm + (uint32_t)(tid * GSTR * 4);
    } else if (tid < 56) {
        int e = tid - 32;
        wsrc = (e < E_) ? Wa + (size_t)e * KDIM : Wi + (size_t)(e - E_) * KDIM;
        dW = wsm + (uint32_t)((tid - 32) * WSTR * 4);
    }

    auto stage = [&](int c) {
        const uint32_t buf  = c & 1;
        const uint32_t mbar = mb0 + buf * 8;
        if (tid < 32) {
            const float* src = (c < NCH / 2) ? (gsrc_a + c * KC)
                                             : (gsrc_i + c * KC - D_);
            expect_tx(mbar, 512);
            bulk512(dG + buf * (GBUF * 4), src, mbar);
        } else if (tid < 56) {
            expect_tx(mbar, 512);
            bulk512(dW + buf * (WBUF * 4), wsrc + c * KC, mbar);
        }
    };

    unsigned long long acc[6][2];
    #pragma unroll
    for (int m = 0; m < 6; m++) { acc[m][0] = 0ULL; acc[m][1] = 0ULL; }

    stage(0);

    for (int c = 0; c < NCH; c++) {
        if (c + 1 < NCH) stage(c + 1);          // writes buffer freed at prev-iter barrier
        wait_parity(mb0 + (c & 1) * 8, (c >> 1) & 1);

        const float* gb = Gm + (c & 1) * GBUF;
        const float* wb = Wm + (c & 1) * WBUF;
        const int cb = ksl * 32;
        #pragma unroll
        for (int kk = 0; kk < 8; kk++) {
            const int col = cb + kk * 4;
            ulonglong2 g0 = *(const ulonglong2*)(gb + r0 * GSTR + col);
            ulonglong2 g1 = *(const ulonglong2*)(gb + (r0 + 8) * GSTR + col);
            #pragma unroll
            for (int m = 0; m < 6; m++) {
                ulonglong2 w = *(const ulonglong2*)(wb + (eg * 6 + m) * WSTR + col);
                ffma2(acc[m][0], g0.x, w.x); ffma2(acc[m][0], g0.y, w.y);
                ffma2(acc[m][1], g1.x, w.x); ffma2(acc[m][1], g1.y, w.y);
            }
        }
        __syncthreads();   // all reads of this buffer done before it is restaged / Lp alias
    }

    // Deposit split-K partials (deterministic order)
    #pragma unroll
    for (int m = 0; m < 6; m++) {
        float2 p0 = unpack2(acc[m][0]);
        float2 p1 = unpack2(acc[m][1]);
        Lp[(ksl * ROWS + r0) * NE + eg * 6 + m]       = p0.x + p0.y;
        Lp[(ksl * ROWS + r0 + 8) * NE + eg * 6 + m]   = p1.x + p1.y;
    }
    __syncthreads();

    // Reduce 4 K-slices in fixed order: 768 sums, 3/thread
    #pragma unroll
    for (int t = 0; t < 3; t++) {
        int idx = tid * 3 + t;
        int r = idx / NE;
        int e = idx - r * NE;
        float s = 0.f;
        #pragma unroll
        for (int k = 0; k < 4; k++) s += Lp[(k * ROWS + r) * NE + e];
        Ls[r * NE + e] = s;
    }
    __syncthreads();

    // Gumbel-softmax straight-through (one thread per row)
    if (tid < ROWS) {
        int b = row0 + tid;
        if (b < B) {
            float* retA = out + (size_t)B * KDIM;
            float* retI = retA + (size_t)B * E_;
            #pragma unroll
            for (int gsel = 0; gsel < 2; gsel++) {
                const float* bias = gsel ? bi : ba;
                const float* gum  = gsel ? gi : ga;
                float* retp       = gsel ? retI : retA;
                float l[E_];
                float mx = -1e30f;
                #pragma unroll
                for (int e = 0; e < E_; e++) {
                    l[e] = Ls[tid * NE + gsel * E_ + e] + bias[e]
                         + gum[(size_t)b * E_ + e];
                    mx = fmaxf(mx, l[e]);
                }
                float s = 0.f;
                float y[E_];
                #pragma unroll
                for (int e = 0; e < E_; e++) { y[e] = expf(l[e] - mx); s += y[e]; }
                const float inv = 1.0f / s;
                float ys[E_];
                int   am = 0;
                float best = y[0] * inv;
                ys[0] = best;
                #pragma unroll
                for (int e = 1; e < E_; e++) {
                    ys[e] = y[e] * inv;
                    if (ys[e] > best) { best = ys[e]; am = e; }  // first-max (jnp.argmax)
                }
                #pragma unroll
                for (int e = 0; e < E_; e++) {
                    float h = (e == am) ? 1.0f : 0.0f;
                    retp[(size_t)b * E_ + e] = (h - ys[e]) + ys[e];  // exact ref arithmetic
                }
                g_scl[gsel * BMAX + b] = ((1.0f - ys[am]) + ys[am]) * (1.0f / 12.0f);
                g_idx[gsel * BMAX + b] = am;
            }
        }
    }
}

// ── Kernel 2: gather — warp per row, 12 independent LDG.128 per lane ──
__global__ void __launch_bounds__(256) gate_gather(
    const float* __restrict__ audio, const float* __restrict__ image,
    float* __restrict__ out, int B)
{
    const int wid  = threadIdx.x >> 5;
    const int lane = threadIdx.x & 31;
    const int b    = blockIdx.x * 8 + wid;
    if (b >= B) return;

    const float sa = g_scl[b];
    const float si = g_scl[BMAX + b];
    const int   ia = g_idx[b];
    const int   ii = g_idx[BMAX + b];

    const float* ap = audio + ((size_t)b * E_ + ia) * D_;
    const float* ip = image + ((size_t)b * E_ + ii) * D_;
    float*       op = out + (size_t)b * KDIM;

    float4 v[12];
    #pragma unroll
    for (int j = 0; j < 6; j++)
        v[j] = *(const float4*)(ap + (lane + 32 * j) * 4);
    #pragma unroll
    for (int j = 0; j < 6; j++)
        v[6 + j] = *(const float4*)(ip + (lane + 32 * j) * 4);

    #pragma unroll
    for (int j = 0; j < 6; j++) {
        float4 t = v[j];
        t.x *= sa; t.y *= sa; t.z *= sa; t.w *= sa;
        *(float4*)(op + (lane + 32 * j) * 4) = t;
    }
    #pragma unroll
    for (int j = 0; j < 6; j++) {
        float4 t = v[6 + j];
        t.x *= si; t.y *= si; t.z *= si; t.w *= si;
        *(float4*)(op + D_ + (lane + 32 * j) * 4) = t;
    }
}

#define SMEM_BYTES (((2 * GBUF + 2 * WBUF + ROWS * NE) * 4) + 16)   // +2 mbarriers

extern "C" void kernel_launch(void* const* d_in, const int* in_sizes, int n_in,
                              void* d_out, int out_size) {
    const float* audio = (const float*)d_in[0];
    const float* image = (const float*)d_in[1];
    const float* Wa    = (const float*)d_in[2];
    const float* ba    = (const float*)d_in[3];
    const float* Wi    = (const float*)d_in[4];
    const float* bi    = (const float*)d_in[5];
    const float* ga    = (const float*)d_in[6];
    const float* gi    = (const float*)d_in[7];
    float* out = (float*)d_out;

    const int B = in_sizes[0] / (E_ * D_);     // 16384

    static bool attr_set = false;
    if (!attr_set) {
        cudaFuncSetAttribute(gate_logits,
                             cudaFuncAttributeMaxDynamicSharedMemorySize, SMEM_BYTES);
        attr_set = true;
    }

    const int grid1 = (B + ROWS - 1) / ROWS;   // 512
    gate_logits<<<grid1, 256, SMEM_BYTES>>>(audio, image, Wa, ba, Wi, bi,
                                            ga, gi, out, B);

    const int grid2 = (B + 7) / 8;             // 2048
    gate_gather<<<grid2, 256>>>(audio, image, out, B);
}

// round 9
// speedup vs baseline: 1.7768x; 1.2740x over previous
#include <cuda_runtime.h>
#include <cstdint>

#define E_    12
#define D_    768
#define KDIM  1536
#define NE    24
#define ROWS  64            // batch rows per CTA tile (K1): grid 256 -> single wave @2/SM
#define KC    128           // K chunk
#define NCH   12            // KDIM / KC
#define GSTR  132           // G row stride (floats): 528B == 16 mod 128 -> conflict-free
#define WSTR  132           // W chunk row stride
#define GBUF  (ROWS * GSTR) // 8448 floats
#define WBUF  (NE * WSTR)   // 3168 floats
#define BMAX  16384
#define NSTG  (ROWS + NE)   // 88 staging threads

// Cross-kernel handoff (static device arrays — allocation-free)
__device__ float g_scl[2 * BMAX];
__device__ int   g_idx[2 * BMAX];

__device__ __forceinline__ void ffma2(unsigned long long &d,
                                      unsigned long long a,
                                      unsigned long long b) {
    asm("fma.rn.f32x2 %0, %1, %2, %0;" : "+l"(d) : "l"(a), "l"(b));
}
__device__ __forceinline__ float2 unpack2(unsigned long long v) {
    float2 r;
    asm("mov.b64 {%0, %1}, %2;" : "=f"(r.x), "=f"(r.y) : "l"(v));
    return r;
}
__device__ __forceinline__ void bulk512(uint32_t dst, const float* src, uint32_t mbar) {
    asm volatile(
        "cp.async.bulk.shared::cluster.global.mbarrier::complete_tx::bytes "
        "[%0], [%1], 512, [%2];"
        :: "r"(dst), "l"(src), "r"(mbar) : "memory");
}
__device__ __forceinline__ void expect_tx(uint32_t mbar, uint32_t bytes) {
    asm volatile("mbarrier.arrive.expect_tx.shared.b64 _, [%0], %1;"
                 :: "r"(mbar), "r"(bytes) : "memory");
}
__device__ __forceinline__ void wait_parity(uint32_t mbar, uint32_t parity) {
    uint32_t done;
    asm volatile(
        "{\n\t.reg .pred p;\n\t"
        "mbarrier.try_wait.parity.acquire.cta.shared::cta.b64 p, [%1], %2;\n\t"
        "selp.b32 %0, 1, 0, p;\n\t}"
        : "=r"(done) : "r"(mbar), "r"(parity) : "memory");
    if (!done) {
        asm volatile(
            "{\n\t.reg .pred P1;\n\t"
            "WL_%=:\n\t"
            "mbarrier.try_wait.parity.acquire.cta.shared::cta.b64 P1, [%0], %1, 0x989680;\n\t"
            "@P1 bra.uni WD_%=;\n\t"
            "bra.uni WL_%=;\n\t"
            "WD_%=:\n\t}"
            :: "r"(mbar), "r"(parity) : "memory");
    }
}

// ── Kernel 1: bulk-async pipelined logits GEMM (4x6 reg tile) + gumbel-softmax-ST ──
__global__ void __launch_bounds__(256, 2) gate_logits(
    const float* __restrict__ audio, const float* __restrict__ image,
    const float* __restrict__ Wa,    const float* __restrict__ ba,
    const float* __restrict__ Wi,    const float* __restrict__ bi,
    const float* __restrict__ ga,    const float* __restrict__ gi,
    float* __restrict__ out, int B)
{
    extern __shared__ float sm[];
    float* Gm = sm;                    // 2 x GBUF (double buffer)
    float* Wm = sm + 2 * GBUF;         // 2 x WBUF (double buffer)
    float* Ls = Wm + 2 * WBUF;         // ROWS x NE reduced logits
    float* Lp = Gm;                    // alias: 4 x ROWS x NE partials (6144 <= 2*GBUF)
    uint32_t mb0;                      // smem addr of mbar[0]; mbar[1] at +8
    {
        uint64_t* mb = (uint64_t*)(Ls + ROWS * NE);
        mb0 = (uint32_t)__cvta_generic_to_shared(mb);
    }

    const int tid  = threadIdx.x;
    const int lane = tid & 31;
    const int wid  = tid >> 5;
    const int ksl  = wid & 3;          // K-slice: floats ksl*32 .. +31 of each chunk
    const int rg   = wid >> 2;         // row group (0..1) of 32 rows
    const int rp   = lane >> 2;        // row base within group (0..7)
    const int eg   = lane & 3;         // expert group: experts eg*6 .. eg*6+5
    const int rb   = rg * 32 + rp;     // rows rb, rb+8, rb+16, rb+24
    const int row0 = blockIdx.x * ROWS;

    const uint32_t gsm = (uint32_t)__cvta_generic_to_shared(Gm);
    const uint32_t wsm = (uint32_t)__cvta_generic_to_shared(Wm);
    const size_t rowstride = (size_t)E_ * D_;   // 9216

    // Init mbarriers: 88 arrivals per phase (one per issuing thread)
    if (tid == 0) {
        asm volatile("mbarrier.init.shared.b64 [%0], 88;" :: "r"(mb0) : "memory");
        asm volatile("mbarrier.init.shared.b64 [%0], 88;" :: "r"(mb0 + 8) : "memory");
        asm volatile("fence.proxy.async.shared::cta;" ::: "memory");
    }
    __syncthreads();

    // Per-thread staging role: tid<64 -> G row, 64<=tid<88 -> W row
    const float* gsrc_a = nullptr;
    const float* gsrc_i = nullptr;
    const float* wsrc   = nullptr;
    uint32_t     dG = 0, dW = 0;
    if (tid < ROWS) {
        int b = row0 + tid; if (b >= B) b = B - 1;
        gsrc_a = audio + (size_t)b * rowstride;
        gsrc_i = image + (size_t)b * rowstride;
        dG = gsm + (uint32_t)(tid * GSTR * 4);
    } else if (tid < NSTG) {
        int e = tid - ROWS;
        wsrc = (e < E_) ? Wa + (size_t)e * KDIM : Wi + (size_t)(e - E_) * KDIM;
        dW = wsm + (uint32_t)((tid - ROWS) * WSTR * 4);
    }

    auto stage = [&](int c) {
        const uint32_t buf  = c & 1;
        const uint32_t mbar = mb0 + buf * 8;
        if (tid < ROWS) {
            const float* src = (c < NCH / 2) ? (gsrc_a + c * KC)
                                             : (gsrc_i + c * KC - D_);
            expect_tx(mbar, 512);
            bulk512(dG + buf * (GBUF * 4), src, mbar);
        } else if (tid < NSTG) {
            expect_tx(mbar, 512);
            bulk512(dW + buf * (WBUF * 4), wsrc + c * KC, mbar);
        }
    };

    unsigned long long acc[4][6];
    #pragma unroll
    for (int j = 0; j < 4; j++)
        #pragma unroll
        for (int m = 0; m < 6; m++) acc[j][m] = 0ULL;

    stage(0);

    for (int c = 0; c < NCH; c++) {
        if (c + 1 < NCH) stage(c + 1);          // writes buffer freed at prev-iter barrier
        wait_parity(mb0 + (c & 1) * 8, (c >> 1) & 1);

        const float* gb = Gm + (c & 1) * GBUF;
        const float* wb = Wm + (c & 1) * WBUF;
        const int cb = ksl * 32;
        #pragma unroll
        for (int kk = 0; kk < 8; kk++) {
            const int col = cb + kk * 4;
            ulonglong2 g[4];
            #pragma unroll
            for (int j = 0; j < 4; j++)
                g[j] = *(const ulonglong2*)(gb + (rb + 8 * j) * GSTR + col);
            #pragma unroll
            for (int m = 0; m < 6; m++) {
                ulonglong2 w = *(const ulonglong2*)(wb + (eg * 6 + m) * WSTR + col);
                #pragma unroll
                for (int j = 0; j < 4; j++) {
                    ffma2(acc[j][m], g[j].x, w.x);
                    ffma2(acc[j][m], g[j].y, w.y);
                }
            }
        }
        __syncthreads();   // all reads of this buffer done before restage / Lp alias
    }

    // Deposit split-K partials (deterministic order)
    #pragma unroll
    for (int j = 0; j < 4; j++)
        #pragma unroll
        for (int m = 0; m < 6; m++) {
            float2 p = unpack2(acc[j][m]);
            Lp[(ksl * ROWS + rb + 8 * j) * NE + eg * 6 + m] = p.x + p.y;
        }
    __syncthreads();

    // Reduce 4 K-slices in fixed order: 1536 sums, 6/thread
    #pragma unroll
    for (int t = 0; t < 6; t++) {
        int idx = tid * 6 + t;
        int r = idx / NE;
        int e = idx - r * NE;
        float s = 0.f;
        #pragma unroll
        for (int k = 0; k < 4; k++) s += Lp[(k * ROWS + r) * NE + e];
        Ls[r * NE + e] = s;
    }
    __syncthreads();

    // Gumbel-softmax straight-through (one thread per row)
    if (tid < ROWS) {
        int b = row0 + tid;
        if (b < B) {
            float* retA = out + (size_t)B * KDIM;
            float* retI = retA + (size_t)B * E_;
            #pragma unroll
            for (int gsel = 0; gsel < 2; gsel++) {
                const float* bias = gsel ? bi : ba;
                const float* gum  = gsel ? gi : ga;
                float* retp       = gsel ? retI : retA;
                float l[E_];
                float mx = -1e30f;
                #pragma unroll
                for (int e = 0; e < E_; e++) {
                    l[e] = Ls[tid * NE + gsel * E_ + e] + bias[e]
                         + gum[(size_t)b * E_ + e];
                    mx = fmaxf(mx, l[e]);
                }
                float s = 0.f;
                float y[E_];
                #pragma unroll
                for (int e = 0; e < E_; e++) { y[e] = expf(l[e] - mx); s += y[e]; }
                const float inv = 1.0f / s;
                float ys[E_];
                int   am = 0;
                float best = y[0] * inv;
                ys[0] = best;
                #pragma unroll
                for (int e = 1; e < E_; e++) {
                    ys[e] = y[e] * inv;
                    if (ys[e] > best) { best = ys[e]; am = e; }  // first-max (jnp.argmax)
                }
                #pragma unroll
                for (int e = 0; e < E_; e++) {
                    float h = (e == am) ? 1.0f : 0.0f;
                    retp[(size_t)b * E_ + e] = (h - ys[e]) + ys[e];  // exact ref arithmetic
                }
                g_scl[gsel * BMAX + b] = ((1.0f - ys[am]) + ys[am]) * (1.0f / 12.0f);
                g_idx[gsel * BMAX + b] = am;
            }
        }
    }
}

// ── Kernel 2: gather — warp per row, 12 independent LDG.128 per lane ──
__global__ void __launch_bounds__(256) gate_gather(
    const float* __restrict__ audio, const float* __restrict__ image,
    float* __restrict__ out, int B)
{
    const int wid  = threadIdx.x >> 5;
    const int lane = threadIdx.x & 31;
    const int b    = blockIdx.x * 8 + wid;
    if (b >= B) return;

    const float sa = g_scl[b];
    const float si = g_scl[BMAX + b];
    const int   ia = g_idx[b];
    const int   ii = g_idx[BMAX + b];

    const float* ap = audio + ((size_t)b * E_ + ia) * D_;
    const float* ip = image + ((size_t)b * E_ + ii) * D_;
    float*       op = out + (size_t)b * KDIM;

    float4 v[12];
    #pragma unroll
    for (int j = 0; j < 6; j++)
        v[j] = *(const float4*)(ap + (lane + 32 * j) * 4);
    #pragma unroll
    for (int j = 0; j < 6; j++)
        v[6 + j] = *(const float4*)(ip + (lane + 32 * j) * 4);

    #pragma unroll
    for (int j = 0; j < 6; j++) {
        float4 t = v[j];
        t.x *= sa; t.y *= sa; t.z *= sa; t.w *= sa;
        *(float4*)(op + (lane + 32 * j) * 4) = t;
    }
    #pragma unroll
    for (int j = 0; j < 6; j++) {
        float4 t = v[6 + j];
        t.x *= si; t.y *= si; t.z *= si; t.w *= si;
        *(float4*)(op + D_ + (lane + 32 * j) * 4) = t;
    }
}

#define SMEM_BYTES (((2 * GBUF + 2 * WBUF + ROWS * NE) * 4) + 16)   // ~99.1 KB

extern "C" void kernel_launch(void* const* d_in, const int* in_sizes, int n_in,
                              void* d_out, int out_size) {
    const float* audio = (const float*)d_in[0];
    const float* image = (const float*)d_in[1];
    const float* Wa    = (const float*)d_in[2];
    const float* ba    = (const float*)d_in[3];
    const float* Wi    = (const float*)d_in[4];
    const float* bi    = (const float*)d_in[5];
    const float* ga    = (const float*)d_in[6];
    const float* gi    = (const float*)d_in[7];
    float* out = (float*)d_out;

    const int B = in_sizes[0] / (E_ * D_);     // 16384

    static bool attr_set = false;
    if (!attr_set) {
        cudaFuncSetAttribute(gate_logits,
                             cudaFuncAttributeMaxDynamicSharedMemorySize, SMEM_BYTES);
        attr_set = true;
    }

    const int grid1 = (B + ROWS - 1) / ROWS;   // 256 -> single wave at 2 CTAs/SM
    gate_logits<<<grid1, 256, SMEM_BYTES>>>(audio, image, Wa, ba, Wi, bi,
                                            ga, gi, out, B);

    const int grid2 = (B + 7) / 8;             // 2048
    gate_gather<<<grid2, 256>>>(audio, image, out, B);
}